// round 15
// baseline (speedup 1.0000x reference)
#include <cuda_runtime.h>
#include <cuda_fp16.h>
#include <cstdint>

#define N_NODES 200000
#define K1      500
#define KK      256        // 512 halves (zero-padded) = 256 half2
#define EMB     128
#define HID     64
#define NCLS    7
#define BM      64
#define NCHUNK  16
#define THREADS 128

#define A_STR   20         // A tile row stride (u32): 16 + 4 pad
#define B_STR   136        // B tile row stride (u32): 128 + 8 pad
#define E_STR   68         // emb half2 / h fp32 row stride
#define W1_STR  72         // W1 row stride (u32)

// byte offsets in dynamic smem (R13-proven 4-CTA layout)
#define OFF_BEMB 0
#define OFF_BRT1 512
#define OFF_BRT2 768       // ends 800
#define OFF_A0   896
#define ABUF     5120                       // 64*A_STR*4
#define OFF_B0   (OFF_A0 + 4*ABUF)          // 21376
#define BBUF     8704                       // 16*B_STR*4
#define OFF_E    OFF_A0                     // overlay: 17408 <= 20480 (A dead)
#define OFF_W1   OFF_B0                     // overlay: 18432 (B dead post stage 1)
#define OFF_W2   (OFF_B0 + 18432)           // 1792B, inside dead B region
#define SMEM_BYTES (OFF_B0 + 4*BBUF)        // 56192 -> 4 CTAs/SM (proven R13)

// prep-packed weights: half2 pairs along k, [kk][n]
__device__ uint32_t g_WembP[KK * EMB];      // [kk][n]
__device__ uint32_t g_W1P[(EMB/2) * HID];   // [kk][n]

__device__ __forceinline__ uint32_t pack2(float a, float b) {
    __half2 h = __floats2half2_rn(a, b);
    return *reinterpret_cast<uint32_t*>(&h);
}
__device__ __forceinline__ void cp16(uint32_t dst, const void* src) {
    asm volatile("cp.async.cg.shared.global [%0], [%1], 16;"
                 :: "r"(dst), "l"(src));
}
__device__ __forceinline__ void mma16(float c[4], const uint32_t a[4], const uint32_t b[2]) {
    asm volatile(
        "mma.sync.aligned.m16n8k16.row.col.f32.f16.f16.f32 "
        "{%0,%1,%2,%3},{%4,%5,%6,%7},{%8,%9},{%0,%1,%2,%3};"
        : "+f"(c[0]), "+f"(c[1]), "+f"(c[2]), "+f"(c[3])
        : "r"(a[0]), "r"(a[1]), "r"(a[2]), "r"(a[3]), "r"(b[0]), "r"(b[1]));
}

// ---------------- prep: pack weights as half2-k-pairs, [kk][n] ----------------
__global__ void prep_kernel(const float* __restrict__ W_emb,
                            const float* __restrict__ W_rt1) {
    int i = blockIdx.x * blockDim.x + threadIdx.x;
    const int T1 = KK * EMB;
    if (i < T1) {
        int kk = i >> 7, n = i & 127;
        float w0 = (2 * kk     < K1) ? W_emb[(size_t)(2 * kk) * EMB + n]     : 0.0f;
        float w1 = (2 * kk + 1 < K1) ? W_emb[(size_t)(2 * kk + 1) * EMB + n] : 0.0f;
        g_WembP[i] = pack2(w0, w1);
    } else if (i < T1 + (EMB/2) * HID) {
        int j = i - T1; int kk = j >> 6, n = j & 63;
        g_W1P[j] = pack2(W_rt1[(2 * kk) * HID + n], W_rt1[(2 * kk + 1) * HID + n]);
    }
}

// ---------------- main fused kernel ----------------
__global__ void __launch_bounds__(THREADS, 4)
policy_deep_kernel(const float* __restrict__ features,
                   const float* __restrict__ b_emb,
                   const float* __restrict__ b_rt1,
                   const float* __restrict__ b_rt2,
                   const float* __restrict__ W_rt2,
                   float* __restrict__ out)
{
    extern __shared__ char smem[];
    const int tid  = threadIdx.x;
    const int warp = tid >> 5, lane = tid & 31;
    const int grp  = lane >> 2, tig = lane & 3;
    const int wm   = (warp >> 1) * 32;     // rows 0 / 32
    const int wn   = (warp & 1) * 64;      // stage-1 cols 0 / 64
    const int row0 = blockIdx.x * BM;
    const uint32_t sbase = (uint32_t)__cvta_generic_to_shared(smem);

    float*    bemb_s = (float*)(smem + OFF_BEMB);
    float*    brt1_s = (float*)(smem + OFF_BRT1);
    float*    brt2_s = (float*)(smem + OFF_BRT2);
    uint32_t* Eu     = (uint32_t*)(smem + OFF_E);
    uint32_t* W1s    = (uint32_t*)(smem + OFF_W1);
    float*    w2_s   = (float*)(smem + OFF_W2);

    for (int i = tid; i < EMB;  i += THREADS) bemb_s[i] = b_emb[i];
    for (int i = tid; i < HID;  i += THREADS) brt1_s[i] = b_rt1[i];
    for (int i = tid; i < NCLS; i += THREADS) brt2_s[i] = b_rt2[i];

    // ---- hoisted A-load machinery (exact grid: no row predicates) ----
    const int r0t  = tid >> 3;              // 0..15
    const int k4t  = (tid & 7) * 4;         // 0,4,..,28
    const float* aBase = features + (size_t)(row0 + r0t) * K1 + k4t;
    const bool k4ok = (k4t <= 16);          // chunk-15 k-validity (gk+4 <= 500)

    auto ldgA = [&](int c, uint4* pf) {
        const float* p = aBase + c * 32;
        const bool kok = (c < 15) | k4ok;
        #pragma unroll
        for (int i = 0; i < 4; i++) {
            if (kok) pf[i] = *(const uint4*)(p + i * 16 * K1);
            else     pf[i] = make_uint4(0, 0, 0, 0);
        }
    };
    const int stsOffU = r0t * A_STR + (tid & 7) * 2;   // u32 units
    auto stsA = [&](const uint4* pf, int buf) {
        uint32_t* Ab = (uint32_t*)(smem + OFF_A0 + buf * ABUF) + stsOffU;
        #pragma unroll
        for (int i = 0; i < 4; i++) {
            uint2 w;
            w.x = pack2(__uint_as_float(pf[i].x), __uint_as_float(pf[i].y));
            w.y = pack2(__uint_as_float(pf[i].z), __uint_as_float(pf[i].w));
            *(uint2*)(Ab + i * 16 * A_STR) = w;
        }
    };
    const int kk0 = tid >> 5;              // 0..3
    const int n4c = (tid & 31) * 4;
    auto cpB = [&](int c, int buf) {
        const uint32_t dbase = sbase + OFF_B0 + (uint32_t)buf * BBUF
                             + (uint32_t)((kk0 * B_STR + n4c) * 4);
        const uint32_t* src = g_WembP + (c * 16 + kk0) * EMB + n4c;
        #pragma unroll
        for (int i = 0; i < 4; i++)
            cp16(dbase + (uint32_t)(i * 4 * B_STR * 4), src + i * 4 * EMB);
    };

    float acc[2][8][4];
    #pragma unroll
    for (int mt = 0; mt < 2; mt++)
        #pragma unroll
        for (int nt = 0; nt < 8; nt++)
            #pragma unroll
            for (int e = 0; e < 4; e++) acc[mt][nt][e] = 0.0f;

    auto mmaChunk = [&](int buf) {
        const uint32_t* Ab = (const uint32_t*)(smem + OFF_A0 + buf * ABUF);
        const uint32_t* Bb = (const uint32_t*)(smem + OFF_B0 + buf * BBUF);
        #pragma unroll
        for (int s = 0; s < 2; s++) {
            uint32_t a[2][4], b[8][2];
            #pragma unroll
            for (int mt = 0; mt < 2; mt++) {
                const int r = wm + mt * 16 + grp;
                a[mt][0] = Ab[r * A_STR + s * 8 + tig];
                a[mt][1] = Ab[(r + 8) * A_STR + s * 8 + tig];
                a[mt][2] = Ab[r * A_STR + s * 8 + tig + 4];
                a[mt][3] = Ab[(r + 8) * A_STR + s * 8 + tig + 4];
            }
            #pragma unroll
            for (int nt = 0; nt < 8; nt++) {
                const int col = wn + nt * 8 + grp;
                b[nt][0] = Bb[(s * 8 + tig) * B_STR + col];
                b[nt][1] = Bb[(s * 8 + tig + 4) * B_STR + col];
            }
            #pragma unroll
            for (int mt = 0; mt < 2; mt++)
                #pragma unroll
                for (int nt = 0; nt < 8; nt++)
                    mma16(acc[mt][nt], a[mt], b[nt]);
        }
    };

    // -------- prologue: B groups 0,1,2 in flight; A0 staged; pf = chunk 1 ----
    uint4 pf[4];
    cpB(0, 0);
    asm volatile("cp.async.commit_group;");
    cpB(1, 1);
    asm volatile("cp.async.commit_group;");
    cpB(2, 2);
    asm volatile("cp.async.commit_group;");
    ldgA(0, pf); stsA(pf, 0);
    ldgA(1, pf);
    asm volatile("cp.async.wait_group 2;");   // B0 done; B1,B2 in flight
    __syncthreads();

    // -------- stage 1: per-chunk sync, 2 groups always in flight --------
    #pragma unroll 1
    for (int c = 0; c < NCHUNK; c++) {
        if (c + 1 < NCHUNK) stsA(pf, (c + 1) & 3);        // pf = chunk c+1
        if (c + 2 < NCHUNK) ldgA(c + 2, pf);
        if (c + 3 < NCHUNK) {
            cpB(c + 3, (c + 3) & 3);
            asm volatile("cp.async.commit_group;");
        }
        mmaChunk(c & 3);
        if (c + 3 < NCHUNK)
            asm volatile("cp.async.wait_group 2;");       // group c+1 done
        else if (c + 2 < NCHUNK)
            asm volatile("cp.async.wait_group 1;");
        else if (c + 1 < NCHUNK)
            asm volatile("cp.async.wait_group 0;");
        __syncthreads();
    }

    // -------- W1 + W2 -> smem (overlay dead B region) --------
    {
        const int kkw = tid >> 4, n4w = (tid & 15) * 4;
        #pragma unroll
        for (int i = 0; i < 8; i++)
            cp16(sbase + OFF_W1 + (uint32_t)(((kkw + i * 8) * W1_STR + n4w) * 4),
                 g_W1P + (kkw + i * 8) * HID + n4w);
        for (int i = tid; i < HID * NCLS; i += THREADS)
            w2_s[i] = W_rt2[i];
        asm volatile("cp.async.commit_group;");
    }

    // -------- epilogue 1: emb = relu(acc + b_emb) as half2 (overlays A bufs) ----
    #pragma unroll
    for (int mt = 0; mt < 2; mt++) {
        #pragma unroll
        for (int nt = 0; nt < 8; nt++) {
            const int r    = wm + mt * 16 + grp;
            const int col  = wn + nt * 8 + tig * 2;
            const int colh = (wn + nt * 8) / 2 + tig;
            const float b0 = bemb_s[col], b1 = bemb_s[col + 1];
            Eu[r * E_STR + colh] =
                pack2(fmaxf(acc[mt][nt][0] + b0, 0.0f), fmaxf(acc[mt][nt][1] + b1, 0.0f));
            Eu[(r + 8) * E_STR + colh] =
                pack2(fmaxf(acc[mt][nt][2] + b0, 0.0f), fmaxf(acc[mt][nt][3] + b1, 0.0f));
        }
    }
    asm volatile("cp.async.wait_group 0;");   // W1 resident
    __syncthreads();

    // -------- stage 2: h = relu(emb @ W_rt1 + b_rt1) --------
    const int wn2 = (warp & 1) * 32;
    float acc2[2][4][4];
    #pragma unroll
    for (int mt = 0; mt < 2; mt++)
        #pragma unroll
        for (int nt = 0; nt < 4; nt++)
            #pragma unroll
            for (int e = 0; e < 4; e++) acc2[mt][nt][e] = 0.0f;

    #pragma unroll
    for (int s = 0; s < 8; s++) {
        uint32_t a[2][4], b[4][2];
        #pragma unroll
        for (int mt = 0; mt < 2; mt++) {
            const int r = wm + mt * 16 + grp;
            a[mt][0] = Eu[r * E_STR + s * 8 + tig];
            a[mt][1] = Eu[(r + 8) * E_STR + s * 8 + tig];
            a[mt][2] = Eu[r * E_STR + s * 8 + tig + 4];
            a[mt][3] = Eu[(r + 8) * E_STR + s * 8 + tig + 4];
        }
        #pragma unroll
        for (int nt = 0; nt < 4; nt++) {
            const int col = wn2 + nt * 8 + grp;
            b[nt][0] = W1s[(s * 8 + tig) * W1_STR + col];
            b[nt][1] = W1s[(s * 8 + tig + 4) * W1_STR + col];
        }
        #pragma unroll
        for (int mt = 0; mt < 2; mt++)
            #pragma unroll
            for (int nt = 0; nt < 4; nt++)
                mma16(acc2[mt][nt], a[mt], b[nt]);
    }
    __syncthreads();   // done reading Eu; reuse region as fp32 h

    float* hs = (float*)(smem + OFF_E);
    #pragma unroll
    for (int mt = 0; mt < 2; mt++) {
        #pragma unroll
        for (int nt = 0; nt < 4; nt++) {
            const int r   = wm + mt * 16 + grp;
            const int col = wn2 + nt * 8 + tig * 2;
            const float b0 = brt1_s[col], b1 = brt1_s[col + 1];
            *(float2*)(hs + r * E_STR + col) =
                make_float2(fmaxf(acc2[mt][nt][0] + b0, 0.0f),
                            fmaxf(acc2[mt][nt][1] + b1, 0.0f));
            *(float2*)(hs + (r + 8) * E_STR + col) =
                make_float2(fmaxf(acc2[mt][nt][2] + b0, 0.0f),
                            fmaxf(acc2[mt][nt][3] + b1, 0.0f));
        }
    }
    __syncthreads();

    // -------- stage 3: out = h @ W_rt2 + b_rt2 --------
    if (warp < 2) {
        const int r  = warp * 32 + lane;
        const int gr = row0 + r;
        float o[NCLS];
        #pragma unroll
        for (int cc = 0; cc < NCLS; cc++) o[cc] = brt2_s[cc];
        #pragma unroll
        for (int k4 = 0; k4 < HID; k4 += 4) {
            float4 h4 = *(const float4*)(hs + r * E_STR + k4);
            const float hh[4] = {h4.x, h4.y, h4.z, h4.w};
            #pragma unroll
            for (int j = 0; j < 4; j++)
                #pragma unroll
                for (int cc = 0; cc < NCLS; cc++)
                    o[cc] = fmaf(hh[j], w2_s[(k4 + j) * NCLS + cc], o[cc]);
        }
        #pragma unroll
        for (int cc = 0; cc < NCLS; cc++)
            out[(size_t)gr * NCLS + cc] = o[cc];
    }
}

extern "C" void kernel_launch(void* const* d_in, const int* in_sizes, int n_in,
                              void* d_out, int out_size) {
    // [0] adj (unused), [1] features, [2] W_emb, [3] b_emb,
    // [4] W_rt1, [5] b_rt1, [6] W_rt2, [7] b_rt2
    const float* features = (const float*)d_in[1];
    const float* W_emb    = (const float*)d_in[2];
    const float* b_emb    = (const float*)d_in[3];
    const float* W_rt1    = (const float*)d_in[4];
    const float* b_rt1    = (const float*)d_in[5];
    const float* W_rt2    = (const float*)d_in[6];
    const float* b_rt2    = (const float*)d_in[7];
    float* out = (float*)d_out;

    const int prep_elems = KK * EMB + (EMB / 2) * HID;
    prep_kernel<<<(prep_elems + 255) / 256, 256>>>(W_emb, W_rt1);

    cudaFuncSetAttribute(policy_deep_kernel,
                         cudaFuncAttributeMaxDynamicSharedMemorySize, SMEM_BYTES);
    const int grid = N_NODES / BM;              // 3125 exactly
    policy_deep_kernel<<<grid, THREADS, SMEM_BYTES>>>(
        features, b_emb, b_rt1, b_rt2, W_rt2, out);
}

// round 16
// speedup vs baseline: 1.3354x; 1.3354x over previous
#include <cuda_runtime.h>
#include <cuda_fp16.h>
#include <cstdint>

#define N_NODES 200000
#define K1      500
#define KK      256        // 512 halves (zero-padded) = 256 half2
#define EMB     128
#define HID     64
#define NCLS    7
#define BM      64
#define NCHUNK  16
#define THREADS 128

#define A_STR   20         // A tile row stride (u32): 16 + 4 pad
#define B_STR   136        // B tile row stride (u32): 128 + 8 pad
#define E_STR   68         // emb half2 / h fp32 row stride
#define W1_STR  72         // W1 row stride (u32)

// byte offsets in dynamic smem (EXACT R11 layout)
#define OFF_BEMB 0
#define OFF_BRT1 512
#define OFF_BRT2 768
#define OFF_W2   832                        // 448 floats -> ends 2624
#define OFF_A0   2688
#define ABUF     5120                       // 64*A_STR*4
#define OFF_B0   (OFF_A0 + 3*ABUF)          // 18048
#define BBUF     8704                       // 16*B_STR*4
#define OFF_E    OFF_A0                     // 17408 B: A bufs (15360) + 2048 of B0
#define OFF_W1   (OFF_B0 + 2048)            // 18432 B; ends 38528 <= 44160
#define SMEM_BYTES (OFF_B0 + 3*BBUF)        // 44160 -> 4 CTAs/SM

// prep-packed weights: half2 pairs along k, [kk][n]
__device__ uint32_t g_WembP[KK * EMB];      // [kk][n]
__device__ uint32_t g_W1P[(EMB/2) * HID];   // [kk][n]

__device__ __forceinline__ uint32_t pack2(float a, float b) {
    __half2 h = __floats2half2_rn(a, b);
    return *reinterpret_cast<uint32_t*>(&h);
}
__device__ __forceinline__ void cp16(uint32_t dst, const void* src) {
    asm volatile("cp.async.cg.shared.global [%0], [%1], 16;"
                 :: "r"(dst), "l"(src));
}
__device__ __forceinline__ void mma16(float c[4], const uint32_t a[4], const uint32_t b[2]) {
    asm volatile(
        "mma.sync.aligned.m16n8k16.row.col.f32.f16.f16.f32 "
        "{%0,%1,%2,%3},{%4,%5,%6,%7},{%8,%9},{%0,%1,%2,%3};"
        : "+f"(c[0]), "+f"(c[1]), "+f"(c[2]), "+f"(c[3])
        : "r"(a[0]), "r"(a[1]), "r"(a[2]), "r"(a[3]), "r"(b[0]), "r"(b[1]));
}

// ---------------- prep: pack weights as half2-k-pairs, [kk][n] ----------------
__global__ void prep_kernel(const float* __restrict__ W_emb,
                            const float* __restrict__ W_rt1) {
    int i = blockIdx.x * blockDim.x + threadIdx.x;
    const int T1 = KK * EMB;
    if (i < T1) {
        int kk = i >> 7, n = i & 127;
        float w0 = (2 * kk     < K1) ? W_emb[(size_t)(2 * kk) * EMB + n]     : 0.0f;
        float w1 = (2 * kk + 1 < K1) ? W_emb[(size_t)(2 * kk + 1) * EMB + n] : 0.0f;
        g_WembP[i] = pack2(w0, w1);
    } else if (i < T1 + (EMB/2) * HID) {
        int j = i - T1; int kk = j >> 6, n = j & 63;
        g_W1P[j] = pack2(W_rt1[(2 * kk) * HID + n], W_rt1[(2 * kk + 1) * HID + n]);
    }
}

// ---------------- main fused kernel (R11 structure, predicates trimmed) -------
__global__ void __launch_bounds__(THREADS, 4)
policy_tri_kernel(const float* __restrict__ features,
                  const float* __restrict__ b_emb,
                  const float* __restrict__ b_rt1,
                  const float* __restrict__ b_rt2,
                  const float* __restrict__ W_rt2,
                  float* __restrict__ out)
{
    extern __shared__ char smem[];
    const int tid  = threadIdx.x;
    const int warp = tid >> 5, lane = tid & 31;
    const int grp  = lane >> 2, tig = lane & 3;
    const int wm   = (warp >> 1) * 32;     // rows 0 / 32
    const int wn   = (warp & 1) * 64;      // stage-1 cols 0 / 64
    const int row0 = blockIdx.x * BM;
    const uint32_t sbase = (uint32_t)__cvta_generic_to_shared(smem);

    float*    bemb_s = (float*)(smem + OFF_BEMB);
    float*    brt1_s = (float*)(smem + OFF_BRT1);
    float*    brt2_s = (float*)(smem + OFF_BRT2);
    float*    w2_s   = (float*)(smem + OFF_W2);
    uint32_t* Eu     = (uint32_t*)(smem + OFF_E);
    uint32_t* W1s    = (uint32_t*)(smem + OFF_W1);

    for (int i = tid; i < EMB;        i += THREADS) bemb_s[i] = b_emb[i];
    for (int i = tid; i < HID;        i += THREADS) brt1_s[i] = b_rt1[i];
    for (int i = tid; i < NCLS;       i += THREADS) brt2_s[i] = b_rt2[i];
    for (int i = tid; i < HID * NCLS; i += THREADS) w2_s[i]   = W_rt2[i];

    // ---- hoisted A-load machinery (exact grid: rows always valid) ----
    const int r0t  = tid >> 3;              // 0..15
    const int k4t  = (tid & 7) * 4;         // 0,4,..,28
    const float* aBase = features + (size_t)(row0 + r0t) * K1 + k4t;
    const bool k4ok = (k4t <= 16);          // chunk-15 k-validity (gk+4 <= 500)

    auto ldgA = [&](int c, uint4* pf) {
        const float* p = aBase + c * 32;
        const bool kok = (c < 15) | k4ok;
        #pragma unroll
        for (int i = 0; i < 4; i++) {
            if (kok) pf[i] = *(const uint4*)(p + i * 16 * K1);
            else     pf[i] = make_uint4(0, 0, 0, 0);
        }
    };
    // thread-constant STS offset into an A buffer
    const int stsOffU = r0t * A_STR + (tid & 7) * 2;   // u32 units
    auto stsA = [&](const uint4* pf, int buf) {
        uint32_t* Ab = (uint32_t*)(smem + OFF_A0 + buf * ABUF) + stsOffU;
        #pragma unroll
        for (int i = 0; i < 4; i++) {
            uint2 w;
            w.x = pack2(__uint_as_float(pf[i].x), __uint_as_float(pf[i].y));
            w.y = pack2(__uint_as_float(pf[i].z), __uint_as_float(pf[i].w));
            *(uint2*)(Ab + i * 16 * A_STR) = w;
        }
    };
    // hoisted cpB offsets
    const int kk0  = tid >> 5;              // 0..3
    const int n4c  = (tid & 31) * 4;
    auto cpB = [&](int c, int buf) {
        const uint32_t dbase = sbase + OFF_B0 + (uint32_t)buf * BBUF
                             + (uint32_t)((kk0 * B_STR + n4c) * 4);
        const uint32_t* src = g_WembP + (c * 16 + kk0) * EMB + n4c;
        #pragma unroll
        for (int i = 0; i < 4; i++)
            cp16(dbase + (uint32_t)(i * 4 * B_STR * 4), src + i * 4 * EMB);
    };

    float acc[2][8][4];
    #pragma unroll
    for (int mt = 0; mt < 2; mt++)
        #pragma unroll
        for (int nt = 0; nt < 8; nt++)
            #pragma unroll
            for (int e = 0; e < 4; e++) acc[mt][nt][e] = 0.0f;

    auto mmaChunk = [&](int buf) {
        const uint32_t* Ab = (const uint32_t*)(smem + OFF_A0 + buf * ABUF);
        const uint32_t* Bb = (const uint32_t*)(smem + OFF_B0 + buf * BBUF);
        #pragma unroll
        for (int s = 0; s < 2; s++) {
            uint32_t a[2][4], b[8][2];
            #pragma unroll
            for (int mt = 0; mt < 2; mt++) {
                const int r = wm + mt * 16 + grp;
                a[mt][0] = Ab[r * A_STR + s * 8 + tig];
                a[mt][1] = Ab[(r + 8) * A_STR + s * 8 + tig];
                a[mt][2] = Ab[r * A_STR + s * 8 + tig + 4];
                a[mt][3] = Ab[(r + 8) * A_STR + s * 8 + tig + 4];
            }
            #pragma unroll
            for (int nt = 0; nt < 8; nt++) {
                const int col = wn + nt * 8 + grp;
                b[nt][0] = Bb[(s * 8 + tig) * B_STR + col];
                b[nt][1] = Bb[(s * 8 + tig + 4) * B_STR + col];
            }
            #pragma unroll
            for (int mt = 0; mt < 2; mt++)
                #pragma unroll
                for (int nt = 0; nt < 8; nt++)
                    mma16(acc[mt][nt], a[mt], b[nt]);
        }
    };

    // -------- prologue (EXACT R11 order) --------
    uint4 pf[4];
    ldgA(0, pf); stsA(pf, 0);
    ldgA(1, pf);
    cpB(0, 0);
    asm volatile("cp.async.commit_group;");
    cpB(1, 1);
    asm volatile("cp.async.commit_group;");
    asm volatile("cp.async.wait_group 1;");   // g0 done; g1 may fly
    __syncthreads();

    // -------- stage 1: prefetch distance 2, one lazy wait per chunk (R11) ----
    int bufC = 0;
    #pragma unroll 1
    for (int c = 0; c < NCHUNK; c++) {
        const int bufN1 = (bufC == 2) ? 0 : bufC + 1;
        const int bufN2 = (bufN1 == 2) ? 0 : bufN1 + 1;
        if (c + 1 < NCHUNK) stsA(pf, bufN1);          // pf holds chunk c+1
        if (c + 2 < NCHUNK) {
            ldgA(c + 2, pf);
            cpB(c + 2, bufN2);
            asm volatile("cp.async.commit_group;");
        }
        mmaChunk(bufC);
        if (c + 2 < NCHUNK)
            asm volatile("cp.async.wait_group 1;");   // group c+1 done
        else
            asm volatile("cp.async.wait_group 0;");   // tail drain
        __syncthreads();
        bufC = bufN1;
    }

    // -------- W1 -> smem (overlays dead B region past E) --------
    {
        const int kkw = tid >> 4, n4w = (tid & 15) * 4;   // 1024 segs / 128 thr
        #pragma unroll
        for (int i = 0; i < 8; i++)
            cp16(sbase + OFF_W1 + (uint32_t)(((kkw + i * 8) * W1_STR + n4w) * 4),
                 g_W1P + (kkw + i * 8) * HID + n4w);
        asm volatile("cp.async.commit_group;");
    }

    // -------- epilogue 1: emb = relu(acc + b_emb) as half2 --------
    #pragma unroll
    for (int mt = 0; mt < 2; mt++) {
        #pragma unroll
        for (int nt = 0; nt < 8; nt++) {
            const int r    = wm + mt * 16 + grp;
            const int col  = wn + nt * 8 + tig * 2;
            const int colh = (wn + nt * 8) / 2 + tig;
            const float b0 = bemb_s[col], b1 = bemb_s[col + 1];
            Eu[r * E_STR + colh] =
                pack2(fmaxf(acc[mt][nt][0] + b0, 0.0f), fmaxf(acc[mt][nt][1] + b1, 0.0f));
            Eu[(r + 8) * E_STR + colh] =
                pack2(fmaxf(acc[mt][nt][2] + b0, 0.0f), fmaxf(acc[mt][nt][3] + b1, 0.0f));
        }
    }
    asm volatile("cp.async.wait_group 0;");   // W1 resident
    __syncthreads();

    // -------- stage 2: h = relu(emb @ W_rt1 + b_rt1) --------
    const int wn2 = (warp & 1) * 32;
    float acc2[2][4][4];
    #pragma unroll
    for (int mt = 0; mt < 2; mt++)
        #pragma unroll
        for (int nt = 0; nt < 4; nt++)
            #pragma unroll
            for (int e = 0; e < 4; e++) acc2[mt][nt][e] = 0.0f;

    #pragma unroll
    for (int s = 0; s < 8; s++) {
        uint32_t a[2][4], b[4][2];
        #pragma unroll
        for (int mt = 0; mt < 2; mt++) {
            const int r = wm + mt * 16 + grp;
            a[mt][0] = Eu[r * E_STR + s * 8 + tig];
            a[mt][1] = Eu[(r + 8) * E_STR + s * 8 + tig];
            a[mt][2] = Eu[r * E_STR + s * 8 + tig + 4];
            a[mt][3] = Eu[(r + 8) * E_STR + s * 8 + tig + 4];
        }
        #pragma unroll
        for (int nt = 0; nt < 4; nt++) {
            const int col = wn2 + nt * 8 + grp;
            b[nt][0] = W1s[(s * 8 + tig) * W1_STR + col];
            b[nt][1] = W1s[(s * 8 + tig + 4) * W1_STR + col];
        }
        #pragma unroll
        for (int mt = 0; mt < 2; mt++)
            #pragma unroll
            for (int nt = 0; nt < 4; nt++)
                mma16(acc2[mt][nt], a[mt], b[nt]);
    }
    __syncthreads();   // done reading Eu; reuse region as fp32 h

    float* hs = (float*)(smem + OFF_E);
    #pragma unroll
    for (int mt = 0; mt < 2; mt++) {
        #pragma unroll
        for (int nt = 0; nt < 4; nt++) {
            const int r   = wm + mt * 16 + grp;
            const int col = wn2 + nt * 8 + tig * 2;
            const float b0 = brt1_s[col], b1 = brt1_s[col + 1];
            *(float2*)(hs + r * E_STR + col) =
                make_float2(fmaxf(acc2[mt][nt][0] + b0, 0.0f),
                            fmaxf(acc2[mt][nt][1] + b1, 0.0f));
            *(float2*)(hs + (r + 8) * E_STR + col) =
                make_float2(fmaxf(acc2[mt][nt][2] + b0, 0.0f),
                            fmaxf(acc2[mt][nt][3] + b1, 0.0f));
        }
    }
    __syncthreads();

    // -------- stage 3: out = h @ W_rt2 + b_rt2 --------
    if (warp < 2) {
        const int r  = warp * 32 + lane;
        const int gr = row0 + r;
        float o[NCLS];
        #pragma unroll
        for (int cc = 0; cc < NCLS; cc++) o[cc] = brt2_s[cc];
        #pragma unroll
        for (int k4 = 0; k4 < HID; k4 += 4) {
            float4 h4 = *(const float4*)(hs + r * E_STR + k4);
            const float hh[4] = {h4.x, h4.y, h4.z, h4.w};
            #pragma unroll
            for (int j = 0; j < 4; j++)
                #pragma unroll
                for (int cc = 0; cc < NCLS; cc++)
                    o[cc] = fmaf(hh[j], w2_s[(k4 + j) * NCLS + cc], o[cc]);
        }
        #pragma unroll
        for (int cc = 0; cc < NCLS; cc++)
            out[(size_t)gr * NCLS + cc] = o[cc];
    }
}

extern "C" void kernel_launch(void* const* d_in, const int* in_sizes, int n_in,
                              void* d_out, int out_size) {
    // [0] adj (unused), [1] features, [2] W_emb, [3] b_emb,
    // [4] W_rt1, [5] b_rt1, [6] W_rt2, [7] b_rt2
    const float* features = (const float*)d_in[1];
    const float* W_emb    = (const float*)d_in[2];
    const float* b_emb    = (const float*)d_in[3];
    const float* W_rt1    = (const float*)d_in[4];
    const float* b_rt1    = (const float*)d_in[5];
    const float* W_rt2    = (const float*)d_in[6];
    const float* b_rt2    = (const float*)d_in[7];
    float* out = (float*)d_out;

    const int prep_elems = KK * EMB + (EMB / 2) * HID;
    prep_kernel<<<(prep_elems + 255) / 256, 256>>>(W_emb, W_rt1);

    cudaFuncSetAttribute(policy_tri_kernel,
                         cudaFuncAttributeMaxDynamicSharedMemorySize, SMEM_BYTES);
    const int grid = N_NODES / BM;              // 3125 exactly
    policy_tri_kernel<<<grid, THREADS, SMEM_BYTES>>>(
        features, b_emb, b_rt1, b_rt2, W_rt2, out);
}